// round 16
// baseline (speedup 1.0000x reference)
#include <cuda_runtime.h>

#define DIM   512
#define CDIM  12
#define NTOK  16384
#define CSIZE 4096
#define GRID  740                 // 148 SMs x 5 CTAs: balanced wave
#define BLK   224                 // 7 warps
#define NWARP 7
#define TOTW  (GRID * NWARP)      // 5180 warps
#define NUNIT 8192                // work units of 2 tokens

#define OUT_OFF_IDX (NTOK * DIM)            // 8388608
#define OUT_OFF_AUX (OUT_OFF_IDX + NTOK)    // 8404992
#define LOG_EPS_NEG 11.512925464970229f     // -ln(1e-5)
#define A_MAX       20.723265837f           // ln(1e9)
#define FULL        0xffffffffu

// ---- device scratch (no allocations allowed) ----
__device__ float g_avg[CSIZE];
__device__ float g_pse;
__device__ int   g_flag = 0;
__device__ int   g_cnt  = 0;

typedef unsigned long long u64;

__device__ __forceinline__ u64 fma2(u64 a, u64 b, u64 c) {
    u64 d; asm("fma.rn.f32x2 %0, %1, %2, %3;" : "=l"(d) : "l"(a), "l"(b), "l"(c));
    return d;
}
__device__ __forceinline__ u64 add2(u64 a, u64 b) {
    u64 d; asm("add.rn.f32x2 %0, %1, %2;" : "=l"(d) : "l"(a), "l"(b));
    return d;
}
__device__ __forceinline__ u64 pack2(float lo, float hi) {
    u64 d; asm("mov.b64 %0, {%1, %2};" : "=l"(d) : "f"(lo), "f"(hi));
    return d;
}
__device__ __forceinline__ float fold2(u64 v) {   // lo + hi
    float lo, hi; asm("mov.b64 {%0, %1}, %2;" : "=f"(lo), "=f"(hi) : "l"(v));
    return lo + hi;
}

// ---------------------------------------------------------------------------
// R15 math (34.9us best) at 5 CTAs/SM: grid 740 x 224, __launch_bounds__(.,5)
// caps regs ~58 (in-proj chunk shrunk 6->4 c's to fit; chunks partition c,
// within-c order identical -> bit-identical sums). Work = 8192 two-token
// units, grid-stride u += 5180: same ~112 tokens/SM spread over 35 warps
// instead of 28 for +25% latency hiding. All per-token code unchanged.
// ---------------------------------------------------------------------------
__global__ void __launch_bounds__(BLK, 5)
mainK(const float* __restrict__ x,
      const float* __restrict__ w_in,
      const float* __restrict__ b_in,
      const float* __restrict__ w_out,
      const float* __restrict__ b_out,
      float* __restrict__ out)
{
    __shared__ float s_wt[CDIM * DIM];   // w_out transposed [c][d]
    __shared__ float s_bm[DIM];          // b_out - S
    __shared__ float s_bp[DIM];          // b_out + S
    __shared__ int   s_last;

    if (blockIdx.x == 0) {
        for (int i = threadIdx.x; i < CSIZE; i += BLK) g_avg[i] = 0.f;
        if (threadIdx.x == 0) g_pse = 0.f;
    }

    const int wid  = threadIdx.x >> 5;
    const int lane = threadIdx.x & 31;
    const int gw   = blockIdx.x * NWARP + wid;         // 0..5179

    // L2-prefetch the second unit's x (2 tokens = 4KB = 32 x 128B lines)
    if (gw + TOTW < NUNIT) {
        const char* pf = (const char*)(x + (size_t)(gw + TOTW) * 2 * DIM);
        asm volatile("prefetch.global.L2 [%0];" :: "l"(pf + lane * 128));
    }

    // stage: transpose w_out, build b_out -+ S  (S = sum_c w_out[d][c])
    for (int d = threadIdx.x; d < DIM; d += BLK) {
        float S = 0.f;
#pragma unroll
        for (int c = 0; c < CDIM; c++) {
            float w = w_out[d * CDIM + c];
            s_wt[c * DIM + d] = w;
            S += w;
        }
        float b = b_out[d];
        s_bm[d] = b - S;
        s_bp[d] = b + S;
    }
    __syncthreads();

    if (blockIdx.x == 0 && threadIdx.x == 0) {
        __threadfence();
        atomicExch(&g_flag, 1);
    }

    const int c_own = (lane >> 1) & 15;                // c owned by this lane
    const float b_lane = (c_own < CDIM) ? __ldg(&b_in[c_own]) : 0.f;

    const ulonglong2* X2  = (const ulonglong2*)x;
    const ulonglong2* W2  = (const ulonglong2*)w_in;
    const ulonglong2* WT2 = (const ulonglong2*)s_wt;
    ulonglong2*       O2  = (ulonglong2*)out;

    float pse_acc = 0.f;      // distributed across all lanes
    bool  flagged = false;

    for (int u = gw; u < NUNIT; u += TOTW) {
        const int tok0 = u * 2;

        // ---- in-projection: packed FFMA2, chunked over c (4 at a time) ----
        float vv[2][CDIM];
#pragma unroll
        for (int ch = 0; ch < 3; ch++) {
            u64 a2[2][4];
#pragma unroll
            for (int cc = 0; cc < 4; cc++) { a2[0][cc] = 0ull; a2[1][cc] = 0ull; }
#pragma unroll
            for (int i = 0; i < 4; i++) {
                const int off = i * 32 + lane;
                ulonglong2 x0 = X2[(size_t)tok0 * 128 + off];
                ulonglong2 x1 = X2[(size_t)(tok0 + 1) * 128 + off];
#pragma unroll
                for (int cc = 0; cc < 4; cc++) {
                    ulonglong2 w = W2[(ch * 4 + cc) * 128 + off];
                    a2[0][cc] = fma2(x0.x, w.x, a2[0][cc]);
                    a2[0][cc] = fma2(x0.y, w.y, a2[0][cc]);
                    a2[1][cc] = fma2(x1.x, w.x, a2[1][cc]);
                    a2[1][cc] = fma2(x1.y, w.y, a2[1][cc]);
                }
            }
#pragma unroll
            for (int cc = 0; cc < 4; cc++) {
                vv[0][ch * 4 + cc] = fold2(a2[0][cc]);
                vv[1][ch * 4 + cc] = fold2(a2[1][cc]);
            }
        }

        if (!flagged) {
            while (*(volatile int*)&g_flag == 0) { }
            flagged = true;
        }

        // ---- reduce-scatter, BOTH tokens interleaved level-major ----
        float r8[2][8];
#pragma unroll
        for (int j = 0; j < 8; j++)
#pragma unroll
            for (int t = 0; t < 2; t++) {
                float hiV  = (j + 8 < CDIM) ? vv[t][j + 8] : 0.f;
                float send = (lane & 16) ? vv[t][j] : hiV;
                float keep = (lane & 16) ? hiV : vv[t][j];
                r8[t][j] = keep + __shfl_xor_sync(FULL, send, 16);
            }
        float r4[2][4];
#pragma unroll
        for (int j = 0; j < 4; j++)
#pragma unroll
            for (int t = 0; t < 2; t++) {
                float send = (lane & 8) ? r8[t][j] : r8[t][j + 4];
                float keep = (lane & 8) ? r8[t][j + 4] : r8[t][j];
                r4[t][j] = keep + __shfl_xor_sync(FULL, send, 8);
            }
        float r2[2][2];
#pragma unroll
        for (int j = 0; j < 2; j++)
#pragma unroll
            for (int t = 0; t < 2; t++) {
                float send = (lane & 4) ? r4[t][j] : r4[t][j + 2];
                float keep = (lane & 4) ? r4[t][j + 2] : r4[t][j];
                r2[t][j] = keep + __shfl_xor_sync(FULL, send, 4);
            }
        float aa2[2];
        int   idx2[2];
        unsigned act2[2];
#pragma unroll
        for (int t = 0; t < 2; t++) {
            float send = (lane & 2) ? r2[t][0] : r2[t][1];
            float keep = (lane & 2) ? r2[t][1] : r2[t][0];
            float r1 = keep + __shfl_xor_sync(FULL, send, 2);
            r1 += __shfl_xor_sync(FULL, r1, 1);

            const float xp = r1 + b_lane;               // xp for c_own
            aa2[t] = 400.f * fabsf(xp);

            unsigned sb = __ballot_sync(FULL, xp > 0.f);
            act2[t]     = __ballot_sync(FULL, aa2[t] < A_MAX) & 0x00555555u;

            // index: compress even bits of sb (bit 2c -> bit c), then reverse
            unsigned e = sb & 0x00555555u;
            e = (e | (e >> 1)) & 0x33333333u;
            e = (e | (e >> 2)) & 0x0F0F0F0Fu;
            e = (e | (e >> 4)) & 0x00FF00FFu;
            e = (e | (e >> 8)) & 0x0000FFFFu;
            idx2[t] = (int)(__brev(e) >> 20);

            if (lane == 0) out[OUT_OFF_IDX + tok0 + t] = (float)idx2[t];
        }

        // ---- per-token: entropy -> out-proj ----
#pragma unroll
        for (int t = 0; t < 2; t++) {
            const float    a   = aa2[t];
            const unsigned act = act2[t];
            const int      idx = idx2[t];

            // ---- entropy (factorized softmax, MUFU transcendentals) ----
            if (act == 0u) {
                if (lane == 0) atomicAdd(&g_avg[idx], 1.f);
            } else {
                const int k = __popc(act);
                float Z = 1.f;
                unsigned mm = act;
                while (mm) {
                    int b = __ffs(mm) - 1;
                    float ac = __shfl_sync(FULL, a, b);
                    Z *= 1.f + __expf(-ac);
                    mm &= mm - 1;
                }
                const float logZ = __logf(Z);
                const float invZ = 1.f / Z;
                const int   n    = 1 << k;
                for (int base = 0; base < n; base += 32) {
                    const int sub = base + lane;
                    float Asum = 0.f;
                    int   ix   = idx, j = 0;
                    mm = act;
                    while (mm) {
                        int b = __ffs(mm) - 1;
                        int c = b >> 1;
                        float ac = __shfl_sync(FULL, a, b);
                        if ((sub >> j) & 1) { Asum += ac; ix ^= 1 << (11 - c); }
                        mm &= mm - 1; j++;
                    }
                    if (sub < n) {
                        float pp = invZ * __expf(-Asum);
                        pse_acc += pp * fminf(Asum + logZ, LOG_EPS_NEG);
                        atomicAdd(&g_avg[ix], pp);
                    }
                }
            }

            // ---- sparse out-projection ----
            const int pc = __popc((unsigned)idx);
            unsigned bits = (pc <= 6) ? (unsigned)idx : (~(unsigned)idx & 0xFFFu);
            const float* bb = (pc <= 6) ? s_bm : s_bp;
            const u64 coef  = pack2(pc <= 6 ? 2.f : -2.f, pc <= 6 ? 2.f : -2.f);

            u64 o[8];
#pragma unroll
            for (int i = 0; i < 8; i++) o[i] = 0ull;
            while (bits) {
                int b = __ffs(bits) - 1;
                int c = 11 - b;
                const ulonglong2* W = WT2 + c * 128;
#pragma unroll
                for (int i = 0; i < 4; i++) {
                    ulonglong2 w = W[i * 32 + lane];
                    o[2 * i]     = add2(o[2 * i],     w.x);
                    o[2 * i + 1] = add2(o[2 * i + 1], w.y);
                }
                bits &= bits - 1;
            }
            const ulonglong2* B2 = (const ulonglong2*)bb;
#pragma unroll
            for (int i = 0; i < 4; i++) {
                ulonglong2 bv = B2[i * 32 + lane];
                ulonglong2 res;
                res.x = fma2(coef, o[2 * i],     bv.x);
                res.y = fma2(coef, o[2 * i + 1], bv.y);
                O2[(size_t)(tok0 + t) * 128 + i * 32 + lane] = res;
            }
        }
    }

    // ---- reduce pse: warp, then block, then global ----
    pse_acc += __shfl_xor_sync(FULL, pse_acc, 16);
    pse_acc += __shfl_xor_sync(FULL, pse_acc, 8);
    pse_acc += __shfl_xor_sync(FULL, pse_acc, 4);
    pse_acc += __shfl_xor_sync(FULL, pse_acc, 2);
    pse_acc += __shfl_xor_sync(FULL, pse_acc, 1);

    __syncthreads();                 // weights dead past here; reuse s_bm
    if (lane == 0) s_bm[wid] = pse_acc;
    __syncthreads();
    if (wid == 0) {
        float v = (lane < NWARP) ? s_bm[lane] : 0.f;
        v += __shfl_xor_sync(FULL, v, 4);
        v += __shfl_xor_sync(FULL, v, 2);
        v += __shfl_xor_sync(FULL, v, 1);
        if (lane == 0) atomicAdd(&g_pse, v);
    }

    // ---- last-block finalize ----
    __threadfence();
    __syncthreads();
    if (threadIdx.x == 0) {
        int old = atomicAdd(&g_cnt, 1);
        s_last = (old == (int)gridDim.x - 1) ? 1 : 0;
    }
    __syncthreads();
    if (s_last) {
        __threadfence();
        const float inv = 1.f / (float)NTOK;
        float ce = 0.f;
        for (int i = threadIdx.x; i < CSIZE; i += BLK) {
            float ap = __ldcg(&g_avg[i]) * inv;
            ce += -ap * __logf(fmaxf(ap, 1e-5f));
        }
        float* red = s_wt;           // reuse smem
        red[threadIdx.x] = ce;
        __syncthreads();
        for (int s = 128; s > 0; s >>= 1) {
            if (threadIdx.x < (unsigned)s && threadIdx.x + s < BLK)
                red[threadIdx.x] += red[threadIdx.x + s];
            __syncthreads();
        }
        if (threadIdx.x == 0) {
            float aux = (__ldcg(&g_pse) * inv - red[0]) * 0.1f;
            out[OUT_OFF_AUX] = aux;
            g_cnt  = 0;
            g_flag = 0;
        }
    }
}

// ---------------------------------------------------------------------------
extern "C" void kernel_launch(void* const* d_in, const int* in_sizes, int n_in,
                              void* d_out, int out_size)
{
    const float* x     = (const float*)d_in[0];
    const float* w_in  = (const float*)d_in[1];
    const float* b_in  = (const float*)d_in[2];
    const float* w_out = (const float*)d_in[3];
    const float* b_out = (const float*)d_in[4];
    float* out = (float*)d_out;

    mainK<<<GRID, BLK>>>(x, w_in, b_in, w_out, b_out, out);
}

// round 17
// speedup vs baseline: 3.5123x; 3.5123x over previous
#include <cuda_runtime.h>

#define DIM   512
#define CDIM  12
#define NTOK  16384
#define CSIZE 4096
#define GRID  592                 // 148 SMs x 4 CTAs: perfectly balanced wave
#define BLK   224                 // 7 warps
#define NWARP 7
#define NWORK 4096                // warp work units (4 tokens each)
#define NPASS 2

#define OUT_OFF_IDX (NTOK * DIM)            // 8388608
#define OUT_OFF_AUX (OUT_OFF_IDX + NTOK)    // 8404992
#define LOG_EPS_NEG 11.512925464970229f     // -ln(1e-5)
#define A_MAX       20.723265837f           // ln(1e9)
#define FULL        0xffffffffu

// ---- device scratch (no allocations allowed) ----
__device__ float g_avg[CSIZE];
__device__ float g_pse;
__device__ int   g_flag = 0;
__device__ int   g_cnt  = 0;

typedef unsigned long long u64;

__device__ __forceinline__ u64 fma2(u64 a, u64 b, u64 c) {
    u64 d; asm("fma.rn.f32x2 %0, %1, %2, %3;" : "=l"(d) : "l"(a), "l"(b), "l"(c));
    return d;
}
__device__ __forceinline__ u64 add2(u64 a, u64 b) {
    u64 d; asm("add.rn.f32x2 %0, %1, %2;" : "=l"(d) : "l"(a), "l"(b));
    return d;
}
__device__ __forceinline__ u64 pack2(float lo, float hi) {
    u64 d; asm("mov.b64 %0, {%1, %2};" : "=l"(d) : "f"(lo), "f"(hi));
    return d;
}
__device__ __forceinline__ float fold2(u64 v) {   // lo + hi
    float lo, hi; asm("mov.b64 {%0, %1}, %2;" : "=f"(lo), "=f"(hi) : "l"(v));
    return lo + hi;
}

// ---------------------------------------------------------------------------
// R15 (34.9us best) + k=1/k=2 entropy specialization. The specialized paths
// are ARITHMETICALLY IDENTICAL to the general subset loop (same op order,
// same Z product order, __expf(0)==1 for the empty subset) — they only
// remove the serial while(mm)/SHFL chains. k>=3 uses the untouched loop.
// NO register caps beyond __launch_bounds__(224,4): R16 proved caps spill.
// 592 x 224 (148 SMs x 4 CTAs x 7 warps), 4 tokens/warp (2 passes x 2).
// ---------------------------------------------------------------------------
__global__ void __launch_bounds__(BLK, 4)
mainK(const float* __restrict__ x,
      const float* __restrict__ w_in,
      const float* __restrict__ b_in,
      const float* __restrict__ w_out,
      const float* __restrict__ b_out,
      float* __restrict__ out)
{
    __shared__ float s_wt[CDIM * DIM];   // w_out transposed [c][d]
    __shared__ float s_bm[DIM];          // b_out - S
    __shared__ float s_bp[DIM];          // b_out + S
    __shared__ int   s_last;

    if (blockIdx.x == 0) {
        for (int i = threadIdx.x; i < CSIZE; i += BLK) g_avg[i] = 0.f;
        if (threadIdx.x == 0) g_pse = 0.f;
    }

    const int wid   = threadIdx.x >> 5;
    const int lane  = threadIdx.x & 31;
    const int gw    = blockIdx.x * NWARP + wid;        // 0..4143

    // L2-prefetch pass-2's x (tokens gw*4+2, gw*4+3: 4KB = 32 x 128B)
    if (gw < NWORK) {
        const char* pf = (const char*)(x + (size_t)(gw * 4 + 2) * DIM);
        asm volatile("prefetch.global.L2 [%0];" :: "l"(pf + lane * 128));
    }

    // stage: transpose w_out, build b_out -+ S  (S = sum_c w_out[d][c])
    for (int d = threadIdx.x; d < DIM; d += BLK) {
        float S = 0.f;
#pragma unroll
        for (int c = 0; c < CDIM; c++) {
            float w = w_out[d * CDIM + c];
            s_wt[c * DIM + d] = w;
            S += w;
        }
        float b = b_out[d];
        s_bm[d] = b - S;
        s_bp[d] = b + S;
    }
    __syncthreads();

    if (blockIdx.x == 0 && threadIdx.x == 0) {
        __threadfence();
        atomicExch(&g_flag, 1);
    }

    const int c_own = (lane >> 1) & 15;                // c owned by this lane
    const float b_lane = (c_own < CDIM) ? __ldg(&b_in[c_own]) : 0.f;

    const ulonglong2* X2  = (const ulonglong2*)x;
    const ulonglong2* W2  = (const ulonglong2*)w_in;
    const ulonglong2* WT2 = (const ulonglong2*)s_wt;
    ulonglong2*       O2  = (ulonglong2*)out;

    float pse_acc = 0.f;      // distributed across all lanes
    bool  flagged = false;

    if (gw < NWORK) {
#pragma unroll
    for (int p = 0; p < NPASS; p++) {
        const int tok0 = gw * 4 + p * 2;

        // ---- in-projection: packed FFMA2, chunked over c (6 at a time) ----
        float vv[2][CDIM];
#pragma unroll
        for (int ch = 0; ch < 2; ch++) {
            u64 a2[2][6];
#pragma unroll
            for (int cc = 0; cc < 6; cc++) { a2[0][cc] = 0ull; a2[1][cc] = 0ull; }
#pragma unroll
            for (int i = 0; i < 4; i++) {
                const int off = i * 32 + lane;
                ulonglong2 x0 = X2[(size_t)tok0 * 128 + off];
                ulonglong2 x1 = X2[(size_t)(tok0 + 1) * 128 + off];
#pragma unroll
                for (int cc = 0; cc < 6; cc++) {
                    ulonglong2 w = W2[(ch * 6 + cc) * 128 + off];
                    a2[0][cc] = fma2(x0.x, w.x, a2[0][cc]);
                    a2[0][cc] = fma2(x0.y, w.y, a2[0][cc]);
                    a2[1][cc] = fma2(x1.x, w.x, a2[1][cc]);
                    a2[1][cc] = fma2(x1.y, w.y, a2[1][cc]);
                }
            }
#pragma unroll
            for (int cc = 0; cc < 6; cc++) {
                vv[0][ch * 6 + cc] = fold2(a2[0][cc]);
                vv[1][ch * 6 + cc] = fold2(a2[1][cc]);
            }
        }

        if (!flagged) {
            while (*(volatile int*)&g_flag == 0) { }
            flagged = true;
        }

        // ---- reduce-scatter, BOTH tokens interleaved level-major ----
        float r8[2][8];
#pragma unroll
        for (int j = 0; j < 8; j++)
#pragma unroll
            for (int t = 0; t < 2; t++) {
                float hiV  = (j + 8 < CDIM) ? vv[t][j + 8] : 0.f;
                float send = (lane & 16) ? vv[t][j] : hiV;
                float keep = (lane & 16) ? hiV : vv[t][j];
                r8[t][j] = keep + __shfl_xor_sync(FULL, send, 16);
            }
        float r4[2][4];
#pragma unroll
        for (int j = 0; j < 4; j++)
#pragma unroll
            for (int t = 0; t < 2; t++) {
                float send = (lane & 8) ? r8[t][j] : r8[t][j + 4];
                float keep = (lane & 8) ? r8[t][j + 4] : r8[t][j];
                r4[t][j] = keep + __shfl_xor_sync(FULL, send, 8);
            }
        float r2[2][2];
#pragma unroll
        for (int j = 0; j < 2; j++)
#pragma unroll
            for (int t = 0; t < 2; t++) {
                float send = (lane & 4) ? r4[t][j] : r4[t][j + 2];
                float keep = (lane & 4) ? r4[t][j + 2] : r4[t][j];
                r2[t][j] = keep + __shfl_xor_sync(FULL, send, 4);
            }
        float aa2[2];
        int   idx2[2];
        unsigned act2[2];
#pragma unroll
        for (int t = 0; t < 2; t++) {
            float send = (lane & 2) ? r2[t][0] : r2[t][1];
            float keep = (lane & 2) ? r2[t][1] : r2[t][0];
            float r1 = keep + __shfl_xor_sync(FULL, send, 2);
            r1 += __shfl_xor_sync(FULL, r1, 1);

            const float xp = r1 + b_lane;               // xp for c_own
            aa2[t] = 400.f * fabsf(xp);

            unsigned sb = __ballot_sync(FULL, xp > 0.f);
            act2[t]     = __ballot_sync(FULL, aa2[t] < A_MAX) & 0x00555555u;

            // index: compress even bits of sb (bit 2c -> bit c), then reverse
            unsigned e = sb & 0x00555555u;
            e = (e | (e >> 1)) & 0x33333333u;
            e = (e | (e >> 2)) & 0x0F0F0F0Fu;
            e = (e | (e >> 4)) & 0x00FF00FFu;
            e = (e | (e >> 8)) & 0x0000FFFFu;
            idx2[t] = (int)(__brev(e) >> 20);

            if (lane == 0) out[OUT_OFF_IDX + tok0 + t] = (float)idx2[t];
        }

        // ---- per-token: entropy -> out-proj ----
#pragma unroll
        for (int t = 0; t < 2; t++) {
            const float    a   = aa2[t];
            const unsigned act = act2[t];
            const int      idx = idx2[t];
            const int      k   = __popc(act);

            // ---- entropy (factorized softmax, MUFU transcendentals) ----
            if (k == 0) {
                if (lane == 0) atomicAdd(&g_avg[idx], 1.f);
            } else if (k == 1) {
                // arithmetic identical to general loop, straight-line
                const int   b0  = __ffs(act) - 1;
                const float ac0 = __shfl_sync(FULL, a, b0);
                const float Z    = 1.f + __expf(-ac0);
                const float logZ = __logf(Z);
                const float invZ = 1.f / Z;
                if (lane < 2) {
                    float Asum = (lane & 1) ? ac0 : 0.f;
                    int   ix   = (lane & 1) ? (idx ^ (1 << (11 - (b0 >> 1)))) : idx;
                    float pp = invZ * __expf(-Asum);
                    pse_acc += pp * fminf(Asum + logZ, LOG_EPS_NEG);
                    atomicAdd(&g_avg[ix], pp);
                }
            } else if (k == 2) {
                const int   b0  = __ffs(act) - 1;
                const int   b1  = 31 - __clz(act);
                const float ac0 = __shfl_sync(FULL, a, b0);
                const float ac1 = __shfl_sync(FULL, a, b1);
                const float Z    = (1.f + __expf(-ac0)) * (1.f + __expf(-ac1));
                const float logZ = __logf(Z);
                const float invZ = 1.f / Z;
                if (lane < 4) {
                    float Asum = 0.f;
                    int   ix   = idx;
                    if (lane & 1) { Asum += ac0; ix ^= 1 << (11 - (b0 >> 1)); }
                    if (lane & 2) { Asum += ac1; ix ^= 1 << (11 - (b1 >> 1)); }
                    float pp = invZ * __expf(-Asum);
                    pse_acc += pp * fminf(Asum + logZ, LOG_EPS_NEG);
                    atomicAdd(&g_avg[ix], pp);
                }
            } else {
                // general path (rare, k >= 3) — unchanged
                float Z = 1.f;
                unsigned mm = act;
                while (mm) {
                    int b = __ffs(mm) - 1;
                    float ac = __shfl_sync(FULL, a, b);
                    Z *= 1.f + __expf(-ac);
                    mm &= mm - 1;
                }
                const float logZ = __logf(Z);
                const float invZ = 1.f / Z;
                const int   n    = 1 << k;
                for (int base = 0; base < n; base += 32) {
                    const int sub = base + lane;
                    float Asum = 0.f;
                    int   ix   = idx, j = 0;
                    mm = act;
                    while (mm) {
                        int b = __ffs(mm) - 1;
                        int c = b >> 1;
                        float ac = __shfl_sync(FULL, a, b);
                        if ((sub >> j) & 1) { Asum += ac; ix ^= 1 << (11 - c); }
                        mm &= mm - 1; j++;
                    }
                    if (sub < n) {
                        float pp = invZ * __expf(-Asum);
                        pse_acc += pp * fminf(Asum + logZ, LOG_EPS_NEG);
                        atomicAdd(&g_avg[ix], pp);
                    }
                }
            }

            // ---- sparse out-projection ----
            const int pc = __popc((unsigned)idx);
            unsigned bits = (pc <= 6) ? (unsigned)idx : (~(unsigned)idx & 0xFFFu);
            const float* bb = (pc <= 6) ? s_bm : s_bp;
            const u64 coef  = pack2(pc <= 6 ? 2.f : -2.f, pc <= 6 ? 2.f : -2.f);

            u64 o[8];
#pragma unroll
            for (int i = 0; i < 8; i++) o[i] = 0ull;
            while (bits) {
                int b = __ffs(bits) - 1;
                int c = 11 - b;
                const ulonglong2* W = WT2 + c * 128;
#pragma unroll
                for (int i = 0; i < 4; i++) {
                    ulonglong2 w = W[i * 32 + lane];
                    o[2 * i]     = add2(o[2 * i],     w.x);
                    o[2 * i + 1] = add2(o[2 * i + 1], w.y);
                }
                bits &= bits - 1;
            }
            const ulonglong2* B2 = (const ulonglong2*)bb;
#pragma unroll
            for (int i = 0; i < 4; i++) {
                ulonglong2 bv = B2[i * 32 + lane];
                ulonglong2 res;
                res.x = fma2(coef, o[2 * i],     bv.x);
                res.y = fma2(coef, o[2 * i + 1], bv.y);
                O2[(size_t)(tok0 + t) * 128 + i * 32 + lane] = res;
            }
        }
    }
    }  // gw < NWORK

    // ---- reduce pse: warp, then block, then global ----
    pse_acc += __shfl_xor_sync(FULL, pse_acc, 16);
    pse_acc += __shfl_xor_sync(FULL, pse_acc, 8);
    pse_acc += __shfl_xor_sync(FULL, pse_acc, 4);
    pse_acc += __shfl_xor_sync(FULL, pse_acc, 2);
    pse_acc += __shfl_xor_sync(FULL, pse_acc, 1);

    __syncthreads();                 // weights dead past here; reuse s_bm
    if (lane == 0) s_bm[wid] = pse_acc;
    __syncthreads();
    if (wid == 0) {
        float v = (lane < NWARP) ? s_bm[lane] : 0.f;
        v += __shfl_xor_sync(FULL, v, 4);
        v += __shfl_xor_sync(FULL, v, 2);
        v += __shfl_xor_sync(FULL, v, 1);
        if (lane == 0) atomicAdd(&g_pse, v);
    }

    // ---- last-block finalize ----
    __threadfence();
    __syncthreads();
    if (threadIdx.x == 0) {
        int old = atomicAdd(&g_cnt, 1);
        s_last = (old == (int)gridDim.x - 1) ? 1 : 0;
    }
    __syncthreads();
    if (s_last) {
        __threadfence();
        const float inv = 1.f / (float)NTOK;
        float ce = 0.f;
        for (int i = threadIdx.x; i < CSIZE; i += BLK) {
            float ap = __ldcg(&g_avg[i]) * inv;
            ce += -ap * __logf(fmaxf(ap, 1e-5f));
        }
        float* red = s_wt;           // reuse smem
        red[threadIdx.x] = ce;
        __syncthreads();
        for (int s = 128; s > 0; s >>= 1) {
            if (threadIdx.x < (unsigned)s && threadIdx.x + s < BLK)
                red[threadIdx.x] += red[threadIdx.x + s];
            __syncthreads();
        }
        if (threadIdx.x == 0) {
            float aux = (__ldcg(&g_pse) * inv - red[0]) * 0.1f;
            out[OUT_OFF_AUX] = aux;
            g_cnt  = 0;
            g_flag = 0;
        }
    }
}

// ---------------------------------------------------------------------------
extern "C" void kernel_launch(void* const* d_in, const int* in_sizes, int n_in,
                              void* d_out, int out_size)
{
    const float* x     = (const float*)d_in[0];
    const float* w_in  = (const float*)d_in[1];
    const float* b_in  = (const float*)d_in[2];
    const float* w_out = (const float*)d_in[3];
    const float* b_out = (const float*)d_in[4];
    float* out = (float*)d_out;

    mainK<<<GRID, BLK>>>(x, w_in, b_in, w_out, b_out, out);
}